// round 10
// baseline (speedup 1.0000x reference)
#include <cuda_runtime.h>
#include <cuda_bf16.h>

// Problem constants (verified against in_sizes at launch)
#define D        128
#define MAX_N    100000
#define MAX_E    3200000
#define CHUNK    1024
#define MAX_BLK  ((MAX_N + CHUNK - 1) / CHUNK)   // 98

// Scratch (__device__ globals per allocation rules)
__device__ float g_h[(size_t)MAX_N * D];      // 51.2 MB: h = x @ W^T
__device__ int   g_count[MAX_N];              // per-dst degree
__device__ int   g_off[MAX_N + 1];            // exclusive offsets
__device__ int   g_cursor[MAX_N];             // fill cursors
__device__ int   g_bsum[MAX_BLK];             // per-block sums
__device__ int   g_boff[MAX_BLK];             // per-block offsets
__device__ int   g_binned_src[MAX_E];         // edges sorted by dst

// ---------------------------------------------------------------------------
// Kernel 1: h = x @ W^T   (fp32 SIMT, W transposed in smem, 4x4 microtile)
// ---------------------------------------------------------------------------
#define WT_LD 132
#define GEMM_SMEM_BYTES ((128 * WT_LD + 32 * 128) * 4)

__global__ void __launch_bounds__(256, 2)
gemm_kernel(const float* __restrict__ x, const float* __restrict__ W, int N) {
    extern __shared__ float smem[];
    float* Wt = smem;                 // [128][WT_LD]  Wt[k][c] = W[c][k]
    float* xs = smem + 128 * WT_LD;   // [32][128]

    const int tid = threadIdx.x;
    const int row0 = blockIdx.x * 32;

    #pragma unroll 4
    for (int i = tid; i < 128 * 128; i += 256) {
        int c = i >> 7, k = i & 127;
        Wt[k * WT_LD + c] = W[i];
    }
    #pragma unroll 4
    for (int i = tid; i < 32 * 128; i += 256) {
        xs[i] = x[(size_t)row0 * D + i];
    }
    __syncthreads();

    const int warp = tid >> 5, lane = tid & 31;
    const int r0 = warp * 4;
    const int c0 = lane * 4;

    float4 acc0 = {0.f,0.f,0.f,0.f};
    float4 acc1 = {0.f,0.f,0.f,0.f};
    float4 acc2 = {0.f,0.f,0.f,0.f};
    float4 acc3 = {0.f,0.f,0.f,0.f};

    #pragma unroll 8
    for (int k0 = 0; k0 < 128; k0 += 4) {
        float4 wv0 = *(const float4*)&Wt[(k0 + 0) * WT_LD + c0];
        float4 wv1 = *(const float4*)&Wt[(k0 + 1) * WT_LD + c0];
        float4 wv2 = *(const float4*)&Wt[(k0 + 2) * WT_LD + c0];
        float4 wv3 = *(const float4*)&Wt[(k0 + 3) * WT_LD + c0];

        float4 xv0 = *(const float4*)&xs[(r0 + 0) * 128 + k0];
        float4 xv1 = *(const float4*)&xs[(r0 + 1) * 128 + k0];
        float4 xv2 = *(const float4*)&xs[(r0 + 2) * 128 + k0];
        float4 xv3 = *(const float4*)&xs[(r0 + 3) * 128 + k0];

        #define STEP(ACC, XV)                                            \
            ACC.x += XV.x * wv0.x; ACC.y += XV.x * wv0.y;                 \
            ACC.z += XV.x * wv0.z; ACC.w += XV.x * wv0.w;                 \
            ACC.x += XV.y * wv1.x; ACC.y += XV.y * wv1.y;                 \
            ACC.z += XV.y * wv1.z; ACC.w += XV.y * wv1.w;                 \
            ACC.x += XV.z * wv2.x; ACC.y += XV.z * wv2.y;                 \
            ACC.z += XV.z * wv2.z; ACC.w += XV.z * wv2.w;                 \
            ACC.x += XV.w * wv3.x; ACC.y += XV.w * wv3.y;                 \
            ACC.z += XV.w * wv3.z; ACC.w += XV.w * wv3.w;
        STEP(acc0, xv0)
        STEP(acc1, xv1)
        STEP(acc2, xv2)
        STEP(acc3, xv3)
        #undef STEP
    }

    float4* hp = (float4*)&g_h[(size_t)(row0 + r0) * D + c0];
    hp[0]           = acc0;
    hp[D / 4]       = acc1;
    hp[2 * (D / 4)] = acc2;
    hp[3 * (D / 4)] = acc3;
}

// ---------------------------------------------------------------------------
// Binning pipeline: counting sort of edges by dst
// ---------------------------------------------------------------------------
__global__ void hist_kernel(const int* __restrict__ ei, int E) {
    int i = blockIdx.x * blockDim.x + threadIdx.x;
    int stride = gridDim.x * blockDim.x;
    for (; i < E; i += stride) {
        atomicAdd(&g_count[ei[E + i]], 1);   // dst row of edge_index
    }
}

// Per-chunk sums of g_count
__global__ void scan1_kernel(int N) {
    __shared__ int s[CHUNK];
    int i = blockIdx.x * CHUNK + threadIdx.x;
    s[threadIdx.x] = (i < N) ? g_count[i] : 0;
    __syncthreads();
    #pragma unroll
    for (int d = CHUNK / 2; d > 0; d >>= 1) {
        if (threadIdx.x < d) s[threadIdx.x] += s[threadIdx.x + d];
        __syncthreads();
    }
    if (threadIdx.x == 0) g_bsum[blockIdx.x] = s[0];
}

// Exclusive scan of block sums (NB <= 128, single block)
__global__ void scan2_kernel(int NB) {
    __shared__ int s[MAX_BLK + 1];
    if (threadIdx.x < NB) s[threadIdx.x] = g_bsum[threadIdx.x];
    __syncthreads();
    if (threadIdx.x == 0) {
        int run = 0;
        for (int b = 0; b < NB; b++) { int v = s[b]; s[b] = run; run += v; }
    }
    __syncthreads();
    if (threadIdx.x < NB) g_boff[threadIdx.x] = s[threadIdx.x];
}

// Per-chunk exclusive scan + base offset -> g_off, g_cursor
__global__ void scan3_kernel(int N) {
    __shared__ int buf0[CHUNK];
    __shared__ int buf1[CHUNK];
    int i = blockIdx.x * CHUNK + threadIdx.x;
    int val = (i < N) ? g_count[i] : 0;

    int* cur = buf0; int* nxt = buf1;
    cur[threadIdx.x] = val;
    __syncthreads();
    #pragma unroll
    for (int d = 1; d < CHUNK; d <<= 1) {             // Hillis-Steele inclusive
        int v = cur[threadIdx.x];
        if (threadIdx.x >= d) v += cur[threadIdx.x - d];
        nxt[threadIdx.x] = v;
        __syncthreads();
        int* t = cur; cur = nxt; nxt = t;
    }
    if (i < N) {
        int excl = cur[threadIdx.x] - val + g_boff[blockIdx.x];
        g_off[i]    = excl;
        g_cursor[i] = excl;
        if (i == N - 1) g_off[N] = excl + val;
    }
}

__global__ void binfill_kernel(const int* __restrict__ ei, int E) {
    int i = blockIdx.x * blockDim.x + threadIdx.x;
    int stride = gridDim.x * blockDim.x;
    for (; i < E; i += stride) {
        int src = ei[i];
        int dst = ei[E + i];
        int pos = atomicAdd(&g_cursor[dst], 1);
        g_binned_src[pos] = src;
    }
}

// ---------------------------------------------------------------------------
// Gather: one warp per destination node, no atomics, single coalesced store.
// Lanes cooperatively load up to 32 bin indices (coalesced), broadcast via
// shfl, accumulate 4-way-interleaved float4s of h rows.
// ---------------------------------------------------------------------------
__global__ void __launch_bounds__(256)
gather_kernel(float* __restrict__ out, int N) {
    const int node = blockIdx.x * 8 + (threadIdx.x >> 5);
    if (node >= N) return;
    const int lane = threadIdx.x & 31;

    const int s = __ldg(&g_off[node]);
    const int e = __ldg(&g_off[node + 1]);

    float4 a0 = {0.f,0.f,0.f,0.f};
    float4 a1 = {0.f,0.f,0.f,0.f};
    float4 a2 = {0.f,0.f,0.f,0.f};
    float4 a3 = {0.f,0.f,0.f,0.f};

    for (int j = s; j < e; j += 32) {
        const int m = min(32, e - j);
        int srcv = (j + lane < e) ? __ldg(&g_binned_src[j + lane]) : 0;

        int b = 0;
        for (; b + 4 <= m; b += 4) {
            int s0 = __shfl_sync(0xFFFFFFFFu, srcv, b);
            int s1 = __shfl_sync(0xFFFFFFFFu, srcv, b + 1);
            int s2 = __shfl_sync(0xFFFFFFFFu, srcv, b + 2);
            int s3 = __shfl_sync(0xFFFFFFFFu, srcv, b + 3);
            float4 v0 = __ldg((const float4*)&g_h[(size_t)s0 * D] + lane);
            float4 v1 = __ldg((const float4*)&g_h[(size_t)s1 * D] + lane);
            float4 v2 = __ldg((const float4*)&g_h[(size_t)s2 * D] + lane);
            float4 v3 = __ldg((const float4*)&g_h[(size_t)s3 * D] + lane);
            a0.x += v0.x; a0.y += v0.y; a0.z += v0.z; a0.w += v0.w;
            a1.x += v1.x; a1.y += v1.y; a1.z += v1.z; a1.w += v1.w;
            a2.x += v2.x; a2.y += v2.y; a2.z += v2.z; a2.w += v2.w;
            a3.x += v3.x; a3.y += v3.y; a3.z += v3.z; a3.w += v3.w;
        }
        for (; b < m; b++) {
            int sb = __shfl_sync(0xFFFFFFFFu, srcv, b);
            float4 v = __ldg((const float4*)&g_h[(size_t)sb * D] + lane);
            a0.x += v.x; a0.y += v.y; a0.z += v.z; a0.w += v.w;
        }
    }

    a0.x += a1.x + a2.x + a3.x;
    a0.y += a1.y + a2.y + a3.y;
    a0.z += a1.z + a2.z + a3.z;
    a0.w += a1.w + a2.w + a3.w;

    *((float4*)&out[(size_t)node * D] + lane) = a0;
}

// ---------------------------------------------------------------------------
extern "C" void kernel_launch(void* const* d_in, const int* in_sizes, int n_in,
                              void* d_out, int out_size) {
    const float* x  = (const float*)d_in[0];   // [N, 128] fp32
    const float* W  = (const float*)d_in[1];   // [128, 128] fp32
    const int*   ei = (const int*)d_in[2];     // [2, E] int32
    float* out = (float*)d_out;                // [N, 128] fp32

    const int N  = in_sizes[0] / D;
    const int E  = in_sizes[2] / 2;
    const int NB = (N + CHUNK - 1) / CHUNK;

    cudaFuncSetAttribute(gemm_kernel,
                         cudaFuncAttributeMaxDynamicSharedMemorySize,
                         GEMM_SMEM_BYTES);

    // Zero the degree histogram (capture-safe: memset on a symbol address).
    void* count_ptr = nullptr;
    cudaGetSymbolAddress(&count_ptr, g_count);
    cudaMemsetAsync(count_ptr, 0, (size_t)N * sizeof(int), 0);

    // GEMM: h = x @ W^T
    gemm_kernel<<<N / 32, 256, GEMM_SMEM_BYTES>>>(x, W, N);

    // Counting sort of edges by dst
    hist_kernel<<<592, 256>>>(ei, E);
    scan1_kernel<<<NB, CHUNK>>>(N);
    scan2_kernel<<<1, 128>>>(NB);
    scan3_kernel<<<NB, CHUNK>>>(N);
    binfill_kernel<<<592, 256>>>(ei, E);

    // Atomic-free gather (writes every output row; no memset of out needed)
    gather_kernel<<<(N + 7) / 8, 256>>>(out, N);
}

// round 11
// speedup vs baseline: 1.1125x; 1.1125x over previous
#include <cuda_runtime.h>
#include <cuda_bf16.h>

// Problem constants (verified against in_sizes at launch)
#define D        128
#define MAX_N    100000
#define MAX_E    3200000
#define CHUNK    1024
#define MAX_BLK  ((MAX_N + CHUNK - 1) / CHUNK)   // 98

// Scratch (__device__ globals per allocation rules)
__device__ float g_h[(size_t)MAX_N * D];      // 51.2 MB: h = x @ W^T
__device__ int   g_count[MAX_N];              // per-dst degree
__device__ int   g_off[MAX_N + 1];            // exclusive offsets
__device__ int   g_cursor[MAX_N];             // fill cursors
__device__ int   g_bsum[MAX_BLK];             // per-block sums
__device__ int   g_boff[MAX_BLK];             // per-block offsets
__device__ int   g_binned_src[MAX_E];         // edges sorted by dst

// ---------------------------------------------------------------------------
// Kernel 1: h = x @ W^T   (fp32 SIMT)
// 64 rows/block, 256 threads (8 warps), 8 rows/warp, 4 cols/lane.
// 12 LDS.128 per 128 FFMA per thread-k-step -> FMA-pipe bound, not LDS bound.
// ---------------------------------------------------------------------------
#define WT_LD   132
#define ROWS_PB 64
#define GEMM_SMEM_BYTES ((128 * WT_LD + ROWS_PB * 128) * 4)   // 100352 B

__global__ void __launch_bounds__(256, 2)
gemm_kernel(const float* __restrict__ x, const float* __restrict__ W, int N) {
    extern __shared__ float smem[];
    float* Wt = smem;                      // [128][WT_LD]  Wt[k][c] = W[c][k]
    float* xs = smem + 128 * WT_LD;        // [64][128]

    const int tid = threadIdx.x;
    const int row0 = blockIdx.x * ROWS_PB;
    const int nrows = min(ROWS_PB, N - row0);

    // Stage W transposed (coalesced global reads)
    #pragma unroll 4
    for (int i = tid; i < 128 * 128; i += 256) {
        int c = i >> 7, k = i & 127;
        Wt[k * WT_LD + c] = W[i];
    }
    // Stage 64 rows of x (zero-pad tail rows)
    #pragma unroll 4
    for (int i = tid; i < ROWS_PB * 128; i += 256) {
        int r = i >> 7;
        xs[i] = (r < nrows) ? x[(size_t)row0 * D + i] : 0.f;
    }
    __syncthreads();

    const int warp = tid >> 5, lane = tid & 31;
    const int r0 = warp * 8;               // 8 rows per warp
    const int c0 = lane * 4;               // 4 cols per lane

    float4 acc[8];
    #pragma unroll
    for (int r = 0; r < 8; r++) acc[r] = make_float4(0.f, 0.f, 0.f, 0.f);

    #pragma unroll 4
    for (int k0 = 0; k0 < 128; k0 += 4) {
        float4 wv0 = *(const float4*)&Wt[(k0 + 0) * WT_LD + c0];
        float4 wv1 = *(const float4*)&Wt[(k0 + 1) * WT_LD + c0];
        float4 wv2 = *(const float4*)&Wt[(k0 + 2) * WT_LD + c0];
        float4 wv3 = *(const float4*)&Wt[(k0 + 3) * WT_LD + c0];

        #pragma unroll
        for (int r = 0; r < 8; r++) {
            float4 xv = *(const float4*)&xs[(r0 + r) * 128 + k0];
            acc[r].x += xv.x * wv0.x; acc[r].y += xv.x * wv0.y;
            acc[r].z += xv.x * wv0.z; acc[r].w += xv.x * wv0.w;
            acc[r].x += xv.y * wv1.x; acc[r].y += xv.y * wv1.y;
            acc[r].z += xv.y * wv1.z; acc[r].w += xv.y * wv1.w;
            acc[r].x += xv.z * wv2.x; acc[r].y += xv.z * wv2.y;
            acc[r].z += xv.z * wv2.z; acc[r].w += xv.z * wv2.w;
            acc[r].x += xv.w * wv3.x; acc[r].y += xv.w * wv3.y;
            acc[r].z += xv.w * wv3.z; acc[r].w += xv.w * wv3.w;
        }
    }

    #pragma unroll
    for (int r = 0; r < 8; r++) {
        int row = r0 + r;
        if (row < nrows) {
            *((float4*)&g_h[(size_t)(row0 + row) * D + c0]) = acc[r];
        }
    }
}

// ---------------------------------------------------------------------------
// Binning pipeline: counting sort of edges by dst
// ---------------------------------------------------------------------------
__global__ void hist_kernel(const int* __restrict__ ei, int E) {
    int i = blockIdx.x * blockDim.x + threadIdx.x;
    int stride = gridDim.x * blockDim.x;
    for (; i < E; i += stride) {
        atomicAdd(&g_count[ei[E + i]], 1);   // dst row of edge_index
    }
}

__global__ void scan1_kernel(int N) {
    __shared__ int s[CHUNK];
    int i = blockIdx.x * CHUNK + threadIdx.x;
    s[threadIdx.x] = (i < N) ? g_count[i] : 0;
    __syncthreads();
    #pragma unroll
    for (int d = CHUNK / 2; d > 0; d >>= 1) {
        if (threadIdx.x < d) s[threadIdx.x] += s[threadIdx.x + d];
        __syncthreads();
    }
    if (threadIdx.x == 0) g_bsum[blockIdx.x] = s[0];
}

__global__ void scan2_kernel(int NB) {
    __shared__ int s[MAX_BLK + 1];
    if (threadIdx.x < NB) s[threadIdx.x] = g_bsum[threadIdx.x];
    __syncthreads();
    if (threadIdx.x == 0) {
        int run = 0;
        for (int b = 0; b < NB; b++) { int v = s[b]; s[b] = run; run += v; }
    }
    __syncthreads();
    if (threadIdx.x < NB) g_boff[threadIdx.x] = s[threadIdx.x];
}

__global__ void scan3_kernel(int N) {
    __shared__ int buf0[CHUNK];
    __shared__ int buf1[CHUNK];
    int i = blockIdx.x * CHUNK + threadIdx.x;
    int val = (i < N) ? g_count[i] : 0;

    int* cur = buf0; int* nxt = buf1;
    cur[threadIdx.x] = val;
    __syncthreads();
    #pragma unroll
    for (int d = 1; d < CHUNK; d <<= 1) {             // Hillis-Steele inclusive
        int v = cur[threadIdx.x];
        if (threadIdx.x >= d) v += cur[threadIdx.x - d];
        nxt[threadIdx.x] = v;
        __syncthreads();
        int* t = cur; cur = nxt; nxt = t;
    }
    if (i < N) {
        int excl = cur[threadIdx.x] - val + g_boff[blockIdx.x];
        g_off[i]    = excl;
        g_cursor[i] = excl;
        if (i == N - 1) g_off[N] = excl + val;
    }
}

__global__ void binfill_kernel(const int* __restrict__ ei, int E) {
    int i = blockIdx.x * blockDim.x + threadIdx.x;
    int stride = gridDim.x * blockDim.x;
    for (; i < E; i += stride) {
        int src = ei[i];
        int dst = ei[E + i];
        int pos = atomicAdd(&g_cursor[dst], 1);
        g_binned_src[pos] = src;
    }
}

// ---------------------------------------------------------------------------
// Gather: one warp per destination node, no atomics, single coalesced store.
// ---------------------------------------------------------------------------
__global__ void __launch_bounds__(256)
gather_kernel(float* __restrict__ out, int N) {
    const int node = blockIdx.x * 8 + (threadIdx.x >> 5);
    if (node >= N) return;
    const int lane = threadIdx.x & 31;

    const int s = __ldg(&g_off[node]);
    const int e = __ldg(&g_off[node + 1]);

    float4 a0 = {0.f,0.f,0.f,0.f};
    float4 a1 = {0.f,0.f,0.f,0.f};
    float4 a2 = {0.f,0.f,0.f,0.f};
    float4 a3 = {0.f,0.f,0.f,0.f};

    for (int j = s; j < e; j += 32) {
        const int m = min(32, e - j);
        int srcv = (j + lane < e) ? __ldg(&g_binned_src[j + lane]) : 0;

        int b = 0;
        for (; b + 4 <= m; b += 4) {
            int s0 = __shfl_sync(0xFFFFFFFFu, srcv, b);
            int s1 = __shfl_sync(0xFFFFFFFFu, srcv, b + 1);
            int s2 = __shfl_sync(0xFFFFFFFFu, srcv, b + 2);
            int s3 = __shfl_sync(0xFFFFFFFFu, srcv, b + 3);
            float4 v0 = __ldg((const float4*)&g_h[(size_t)s0 * D] + lane);
            float4 v1 = __ldg((const float4*)&g_h[(size_t)s1 * D] + lane);
            float4 v2 = __ldg((const float4*)&g_h[(size_t)s2 * D] + lane);
            float4 v3 = __ldg((const float4*)&g_h[(size_t)s3 * D] + lane);
            a0.x += v0.x; a0.y += v0.y; a0.z += v0.z; a0.w += v0.w;
            a1.x += v1.x; a1.y += v1.y; a1.z += v1.z; a1.w += v1.w;
            a2.x += v2.x; a2.y += v2.y; a2.z += v2.z; a2.w += v2.w;
            a3.x += v3.x; a3.y += v3.y; a3.z += v3.z; a3.w += v3.w;
        }
        for (; b < m; b++) {
            int sb = __shfl_sync(0xFFFFFFFFu, srcv, b);
            float4 v = __ldg((const float4*)&g_h[(size_t)sb * D] + lane);
            a0.x += v.x; a0.y += v.y; a0.z += v.z; a0.w += v.w;
        }
    }

    a0.x += a1.x + a2.x + a3.x;
    a0.y += a1.y + a2.y + a3.y;
    a0.z += a1.z + a2.z + a3.z;
    a0.w += a1.w + a2.w + a3.w;

    *((float4*)&out[(size_t)node * D] + lane) = a0;
}

// ---------------------------------------------------------------------------
extern "C" void kernel_launch(void* const* d_in, const int* in_sizes, int n_in,
                              void* d_out, int out_size) {
    const float* x  = (const float*)d_in[0];   // [N, 128] fp32
    const float* W  = (const float*)d_in[1];   // [128, 128] fp32
    const int*   ei = (const int*)d_in[2];     // [2, E] int32
    float* out = (float*)d_out;                // [N, 128] fp32

    const int N  = in_sizes[0] / D;
    const int E  = in_sizes[2] / 2;
    const int NB = (N + CHUNK - 1) / CHUNK;

    // One-time handle creation (host objects only; no device memory).
    static cudaStream_t s_gemm = nullptr;
    static cudaEvent_t  ev_fork = nullptr, ev_gemm = nullptr;
    if (!s_gemm) {
        cudaStreamCreateWithFlags(&s_gemm, cudaStreamNonBlocking);
        cudaEventCreateWithFlags(&ev_fork, cudaEventDisableTiming);
        cudaEventCreateWithFlags(&ev_gemm, cudaEventDisableTiming);
        cudaFuncSetAttribute(gemm_kernel,
                             cudaFuncAttributeMaxDynamicSharedMemorySize,
                             GEMM_SMEM_BYTES);
    }

    void* count_ptr = nullptr;
    cudaGetSymbolAddress(&count_ptr, g_count);

    // ---- Fork: GEMM on side stream, binning chain on the main stream ----
    cudaEventRecord(ev_fork, 0);
    cudaStreamWaitEvent(s_gemm, ev_fork, 0);

    gemm_kernel<<<(N + ROWS_PB - 1) / ROWS_PB, 256, GEMM_SMEM_BYTES, s_gemm>>>(x, W, N);
    cudaEventRecord(ev_gemm, s_gemm);

    // Binning chain (independent of GEMM)
    cudaMemsetAsync(count_ptr, 0, (size_t)N * sizeof(int), 0);
    hist_kernel<<<592, 256>>>(ei, E);
    scan1_kernel<<<NB, CHUNK>>>(N);
    scan2_kernel<<<1, 128>>>(NB);
    scan3_kernel<<<NB, CHUNK>>>(N);
    binfill_kernel<<<592, 256>>>(ei, E);

    // ---- Join: gather needs both g_h and the bins ----
    cudaStreamWaitEvent(0, ev_gemm, 0);
    gather_kernel<<<(N + 7) / 8, 256>>>(out, N);
}

// round 12
// speedup vs baseline: 1.1183x; 1.0052x over previous
#include <cuda_runtime.h>
#include <cuda_bf16.h>

// Problem constants (verified against in_sizes at launch)
#define D        128
#define MAX_N    100000
#define MAX_E    3200000
#define CHUNK    1024
#define MAX_BLK  ((MAX_N + CHUNK - 1) / CHUNK)   // 98

// Scratch (__device__ globals per allocation rules)
__device__ float g_h[(size_t)MAX_N * D];      // 51.2 MB: h = x @ W^T
__device__ int   g_count[MAX_N];              // per-dst degree
__device__ int   g_off[MAX_N + 1];            // exclusive offsets
__device__ int   g_cursor[MAX_N];             // fill cursors
__device__ int   g_bsum[MAX_BLK];             // per-block sums
__device__ int   g_boff[MAX_BLK];             // per-block offsets
__device__ int   g_binned_src[MAX_E];         // edges sorted by dst

// ---------------------------------------------------------------------------
// Kernel 1: h = x @ W^T   (fp32 SIMT)
// 64 rows/block, 256 threads (8 warps), 8 rows/warp, 4 cols/lane.
// 12 LDS.128 per 128 FFMA per thread-k-step -> FMA-pipe bound, not LDS bound.
// ---------------------------------------------------------------------------
#define WT_LD   132
#define ROWS_PB 64
#define GEMM_SMEM_BYTES ((128 * WT_LD + ROWS_PB * 128) * 4)   // 100352 B

__global__ void __launch_bounds__(256, 2)
gemm_kernel(const float* __restrict__ x, const float* __restrict__ W, int N) {
    extern __shared__ float smem[];
    float* Wt = smem;                      // [128][WT_LD]  Wt[k][c] = W[c][k]
    float* xs = smem + 128 * WT_LD;        // [64][128]

    const int tid = threadIdx.x;
    const int row0 = blockIdx.x * ROWS_PB;
    const int nrows = min(ROWS_PB, N - row0);

    // Stage W transposed (coalesced global reads)
    #pragma unroll 4
    for (int i = tid; i < 128 * 128; i += 256) {
        int c = i >> 7, k = i & 127;
        Wt[k * WT_LD + c] = W[i];
    }
    // Stage 64 rows of x (zero-pad tail rows)
    #pragma unroll 4
    for (int i = tid; i < ROWS_PB * 128; i += 256) {
        int r = i >> 7;
        xs[i] = (r < nrows) ? x[(size_t)row0 * D + i] : 0.f;
    }
    __syncthreads();

    const int warp = tid >> 5, lane = tid & 31;
    const int r0 = warp * 8;               // 8 rows per warp
    const int c0 = lane * 4;               // 4 cols per lane

    float4 acc[8];
    #pragma unroll
    for (int r = 0; r < 8; r++) acc[r] = make_float4(0.f, 0.f, 0.f, 0.f);

    #pragma unroll 4
    for (int k0 = 0; k0 < 128; k0 += 4) {
        float4 wv0 = *(const float4*)&Wt[(k0 + 0) * WT_LD + c0];
        float4 wv1 = *(const float4*)&Wt[(k0 + 1) * WT_LD + c0];
        float4 wv2 = *(const float4*)&Wt[(k0 + 2) * WT_LD + c0];
        float4 wv3 = *(const float4*)&Wt[(k0 + 3) * WT_LD + c0];

        #pragma unroll
        for (int r = 0; r < 8; r++) {
            float4 xv = *(const float4*)&xs[(r0 + r) * 128 + k0];
            acc[r].x += xv.x * wv0.x; acc[r].y += xv.x * wv0.y;
            acc[r].z += xv.x * wv0.z; acc[r].w += xv.x * wv0.w;
            acc[r].x += xv.y * wv1.x; acc[r].y += xv.y * wv1.y;
            acc[r].z += xv.y * wv1.z; acc[r].w += xv.y * wv1.w;
            acc[r].x += xv.z * wv2.x; acc[r].y += xv.z * wv2.y;
            acc[r].z += xv.z * wv2.z; acc[r].w += xv.z * wv2.w;
            acc[r].x += xv.w * wv3.x; acc[r].y += xv.w * wv3.y;
            acc[r].z += xv.w * wv3.z; acc[r].w += xv.w * wv3.w;
        }
    }

    #pragma unroll
    for (int r = 0; r < 8; r++) {
        int row = r0 + r;
        if (row < nrows) {
            *((float4*)&g_h[(size_t)(row0 + row) * D + c0]) = acc[r];
        }
    }
}

// ---------------------------------------------------------------------------
// Binning pipeline: counting sort of edges by dst
// ---------------------------------------------------------------------------
__global__ void hist_kernel(const int* __restrict__ ei, int E) {
    int i = blockIdx.x * blockDim.x + threadIdx.x;
    int stride = gridDim.x * blockDim.x;
    for (; i < E; i += stride) {
        atomicAdd(&g_count[ei[E + i]], 1);   // dst row of edge_index
    }
}

__global__ void scan1_kernel(int N) {
    __shared__ int s[CHUNK];
    int i = blockIdx.x * CHUNK + threadIdx.x;
    s[threadIdx.x] = (i < N) ? g_count[i] : 0;
    __syncthreads();
    #pragma unroll
    for (int d = CHUNK / 2; d > 0; d >>= 1) {
        if (threadIdx.x < d) s[threadIdx.x] += s[threadIdx.x + d];
        __syncthreads();
    }
    if (threadIdx.x == 0) g_bsum[blockIdx.x] = s[0];
}

__global__ void scan2_kernel(int NB) {
    __shared__ int s[MAX_BLK + 1];
    if (threadIdx.x < NB) s[threadIdx.x] = g_bsum[threadIdx.x];
    __syncthreads();
    if (threadIdx.x == 0) {
        int run = 0;
        for (int b = 0; b < NB; b++) { int v = s[b]; s[b] = run; run += v; }
    }
    __syncthreads();
    if (threadIdx.x < NB) g_boff[threadIdx.x] = s[threadIdx.x];
}

__global__ void scan3_kernel(int N) {
    __shared__ int buf0[CHUNK];
    __shared__ int buf1[CHUNK];
    int i = blockIdx.x * CHUNK + threadIdx.x;
    int val = (i < N) ? g_count[i] : 0;

    int* cur = buf0; int* nxt = buf1;
    cur[threadIdx.x] = val;
    __syncthreads();
    #pragma unroll
    for (int d = 1; d < CHUNK; d <<= 1) {             // Hillis-Steele inclusive
        int v = cur[threadIdx.x];
        if (threadIdx.x >= d) v += cur[threadIdx.x - d];
        nxt[threadIdx.x] = v;
        __syncthreads();
        int* t = cur; cur = nxt; nxt = t;
    }
    if (i < N) {
        int excl = cur[threadIdx.x] - val + g_boff[blockIdx.x];
        g_off[i]    = excl;
        g_cursor[i] = excl;
        if (i == N - 1) g_off[N] = excl + val;
    }
}

__global__ void binfill_kernel(const int* __restrict__ ei, int E) {
    int i = blockIdx.x * blockDim.x + threadIdx.x;
    int stride = gridDim.x * blockDim.x;
    for (; i < E; i += stride) {
        int src = ei[i];
        int dst = ei[E + i];
        int pos = atomicAdd(&g_cursor[dst], 1);
        g_binned_src[pos] = src;
    }
}

// ---------------------------------------------------------------------------
// Gather: one warp per destination node, no atomics, single coalesced store.
// ---------------------------------------------------------------------------
__global__ void __launch_bounds__(256)
gather_kernel(float* __restrict__ out, int N) {
    const int node = blockIdx.x * 8 + (threadIdx.x >> 5);
    if (node >= N) return;
    const int lane = threadIdx.x & 31;

    const int s = __ldg(&g_off[node]);
    const int e = __ldg(&g_off[node + 1]);

    float4 a0 = {0.f,0.f,0.f,0.f};
    float4 a1 = {0.f,0.f,0.f,0.f};
    float4 a2 = {0.f,0.f,0.f,0.f};
    float4 a3 = {0.f,0.f,0.f,0.f};

    for (int j = s; j < e; j += 32) {
        const int m = min(32, e - j);
        int srcv = (j + lane < e) ? __ldg(&g_binned_src[j + lane]) : 0;

        int b = 0;
        for (; b + 4 <= m; b += 4) {
            int s0 = __shfl_sync(0xFFFFFFFFu, srcv, b);
            int s1 = __shfl_sync(0xFFFFFFFFu, srcv, b + 1);
            int s2 = __shfl_sync(0xFFFFFFFFu, srcv, b + 2);
            int s3 = __shfl_sync(0xFFFFFFFFu, srcv, b + 3);
            float4 v0 = __ldg((const float4*)&g_h[(size_t)s0 * D] + lane);
            float4 v1 = __ldg((const float4*)&g_h[(size_t)s1 * D] + lane);
            float4 v2 = __ldg((const float4*)&g_h[(size_t)s2 * D] + lane);
            float4 v3 = __ldg((const float4*)&g_h[(size_t)s3 * D] + lane);
            a0.x += v0.x; a0.y += v0.y; a0.z += v0.z; a0.w += v0.w;
            a1.x += v1.x; a1.y += v1.y; a1.z += v1.z; a1.w += v1.w;
            a2.x += v2.x; a2.y += v2.y; a2.z += v2.z; a2.w += v2.w;
            a3.x += v3.x; a3.y += v3.y; a3.z += v3.z; a3.w += v3.w;
        }
        for (; b < m; b++) {
            int sb = __shfl_sync(0xFFFFFFFFu, srcv, b);
            float4 v = __ldg((const float4*)&g_h[(size_t)sb * D] + lane);
            a0.x += v.x; a0.y += v.y; a0.z += v.z; a0.w += v.w;
        }
    }

    a0.x += a1.x + a2.x + a3.x;
    a0.y += a1.y + a2.y + a3.y;
    a0.z += a1.z + a2.z + a3.z;
    a0.w += a1.w + a2.w + a3.w;

    *((float4*)&out[(size_t)node * D] + lane) = a0;
}

// ---------------------------------------------------------------------------
extern "C" void kernel_launch(void* const* d_in, const int* in_sizes, int n_in,
                              void* d_out, int out_size) {
    const float* x  = (const float*)d_in[0];   // [N, 128] fp32
    const float* W  = (const float*)d_in[1];   // [128, 128] fp32
    const int*   ei = (const int*)d_in[2];     // [2, E] int32
    float* out = (float*)d_out;                // [N, 128] fp32

    const int N  = in_sizes[0] / D;
    const int E  = in_sizes[2] / 2;
    const int NB = (N + CHUNK - 1) / CHUNK;

    // One-time handle creation (host objects only; no device memory).
    static cudaStream_t s_gemm = nullptr;
    static cudaEvent_t  ev_fork = nullptr, ev_gemm = nullptr;
    if (!s_gemm) {
        cudaStreamCreateWithFlags(&s_gemm, cudaStreamNonBlocking);
        cudaEventCreateWithFlags(&ev_fork, cudaEventDisableTiming);
        cudaEventCreateWithFlags(&ev_gemm, cudaEventDisableTiming);
        cudaFuncSetAttribute(gemm_kernel,
                             cudaFuncAttributeMaxDynamicSharedMemorySize,
                             GEMM_SMEM_BYTES);
    }

    void* count_ptr = nullptr;
    cudaGetSymbolAddress(&count_ptr, g_count);

    // ---- Fork: GEMM on side stream, binning chain on the main stream ----
    cudaEventRecord(ev_fork, 0);
    cudaStreamWaitEvent(s_gemm, ev_fork, 0);

    gemm_kernel<<<(N + ROWS_PB - 1) / ROWS_PB, 256, GEMM_SMEM_BYTES, s_gemm>>>(x, W, N);
    cudaEventRecord(ev_gemm, s_gemm);

    // Binning chain (independent of GEMM)
    cudaMemsetAsync(count_ptr, 0, (size_t)N * sizeof(int), 0);
    hist_kernel<<<592, 256>>>(ei, E);
    scan1_kernel<<<NB, CHUNK>>>(N);
    scan2_kernel<<<1, 128>>>(NB);
    scan3_kernel<<<NB, CHUNK>>>(N);
    binfill_kernel<<<592, 256>>>(ei, E);

    // ---- Join: gather needs both g_h and the bins ----
    cudaStreamWaitEvent(0, ev_gemm, 0);
    gather_kernel<<<(N + 7) / 8, 256>>>(out, N);
}

// round 13
// speedup vs baseline: 1.1512x; 1.0294x over previous
#include <cuda_runtime.h>
#include <cuda_bf16.h>

// Problem constants (verified against in_sizes at launch)
#define D        128
#define MAX_N    100000
#define MAX_E    3200000
#define CHUNK    1024
#define MAX_BLK  ((MAX_N + CHUNK - 1) / CHUNK)   // 98

// Scratch (__device__ globals per allocation rules)
__device__ float g_h[(size_t)MAX_N * D];      // 51.2 MB: h = x @ W^T
__device__ int   g_count[MAX_N];              // per-dst degree
__device__ int   g_off[MAX_N + 1];            // exclusive offsets
__device__ int   g_cursor[MAX_N];             // fill cursors
__device__ int   g_bsum[MAX_BLK];             // per-block sums
__device__ int   g_boff[MAX_BLK];             // per-block offsets
__device__ int   g_binned_src[MAX_E];         // edges sorted by dst

// ---------------------------------------------------------------------------
// Kernel 1: h = x @ W^T   (fp32 SIMT with packed fma.rn.f32x2)
// 64 rows/block, 256 threads (8 warps), 8 rows/warp (4 row-PAIRS), 4 cols/lane.
// x staged TRANSPOSED so a row-pair is one LDS.64 broadcast; W scalars are
// splatted to (w,w) pairs once per k and amortized over 4 row-pairs.
// Inner k-step: 16 FFMA2 instead of 32 FFMA -> FMA-pipe time halves.
// ---------------------------------------------------------------------------
#define WT_LD   132
#define XS_LD   66                       // even (8B-aligned pairs), 2-way staging conflicts only
#define ROWS_PB 64
#define GEMM_SMEM_BYTES ((128 * WT_LD + 128 * XS_LD) * 4)   // 101376 B

__device__ __forceinline__ unsigned long long pack2(float f) {
    unsigned long long r;
    unsigned int u = __float_as_uint(f);
    asm("mov.b64 %0, {%1, %1};" : "=l"(r) : "r"(u));
    return r;
}
__device__ __forceinline__ void fma2(unsigned long long& d,
                                     unsigned long long a,
                                     unsigned long long b) {
    asm("fma.rn.f32x2 %0, %1, %2, %0;" : "+l"(d) : "l"(a), "l"(b));
}
__device__ __forceinline__ void unpack2(unsigned long long v, float& lo, float& hi) {
    unsigned int ulo, uhi;
    asm("mov.b64 {%0, %1}, %2;" : "=r"(ulo), "=r"(uhi) : "l"(v));
    lo = __uint_as_float(ulo);
    hi = __uint_as_float(uhi);
}

__global__ void __launch_bounds__(256, 2)
gemm_kernel(const float* __restrict__ x, const float* __restrict__ W, int N) {
    extern __shared__ float smem[];
    float* Wt  = smem;                     // [128][WT_LD]  Wt[k][c] = W[c][k]
    float* xst = smem + 128 * WT_LD;       // [128][XS_LD]  xst[k][r] = x[row0+r][k]

    const int tid = threadIdx.x;
    const int row0 = blockIdx.x * ROWS_PB;
    const int nrows = min(ROWS_PB, N - row0);

    // Stage W transposed (coalesced global reads)
    #pragma unroll 4
    for (int i = tid; i < 128 * 128; i += 256) {
        int c = i >> 7, k = i & 127;
        Wt[k * WT_LD + c] = W[i];
    }
    // Stage x transposed: coalesced global read (k fastest), transposed smem write
    #pragma unroll 4
    for (int i = tid; i < ROWS_PB * 128; i += 256) {
        int r = i >> 7, k = i & 127;
        xst[k * XS_LD + r] = (r < nrows) ? x[(size_t)row0 * D + i] : 0.f;
    }
    __syncthreads();

    const int warp = tid >> 5, lane = tid & 31;
    const int r0 = warp * 8;               // 8 rows = 4 row-pairs per warp
    const int c0 = lane * 4;               // 4 cols per lane

    unsigned long long acc[4][4];           // [row-pair][col] packed f32x2 (lo=even row)
    #pragma unroll
    for (int p = 0; p < 4; p++)
        #pragma unroll
        for (int c = 0; c < 4; c++) acc[p][c] = 0ull;

    #pragma unroll 4
    for (int k = 0; k < 128; k++) {
        float4 wv = *(const float4*)&Wt[k * WT_LD + c0];
        unsigned long long w0 = pack2(wv.x);
        unsigned long long w1 = pack2(wv.y);
        unsigned long long w2 = pack2(wv.z);
        unsigned long long w3 = pack2(wv.w);

        const unsigned long long* xp =
            (const unsigned long long*)&xst[k * XS_LD + r0];
        unsigned long long x0 = xp[0];      // rows (r0,   r0+1)  broadcast LDS.64
        unsigned long long x1 = xp[1];      // rows (r0+2, r0+3)
        unsigned long long x2 = xp[2];
        unsigned long long x3 = xp[3];

        fma2(acc[0][0], x0, w0); fma2(acc[0][1], x0, w1);
        fma2(acc[0][2], x0, w2); fma2(acc[0][3], x0, w3);
        fma2(acc[1][0], x1, w0); fma2(acc[1][1], x1, w1);
        fma2(acc[1][2], x1, w2); fma2(acc[1][3], x1, w3);
        fma2(acc[2][0], x2, w0); fma2(acc[2][1], x2, w1);
        fma2(acc[2][2], x2, w2); fma2(acc[2][3], x2, w3);
        fma2(acc[3][0], x3, w0); fma2(acc[3][1], x3, w1);
        fma2(acc[3][2], x3, w2); fma2(acc[3][3], x3, w3);
    }

    #pragma unroll
    for (int p = 0; p < 4; p++) {
        const int rlo = r0 + 2 * p;
        float4 vlo, vhi;
        unpack2(acc[p][0], vlo.x, vhi.x);
        unpack2(acc[p][1], vlo.y, vhi.y);
        unpack2(acc[p][2], vlo.z, vhi.z);
        unpack2(acc[p][3], vlo.w, vhi.w);
        if (rlo < nrows)
            *((float4*)&g_h[(size_t)(row0 + rlo) * D + c0]) = vlo;
        if (rlo + 1 < nrows)
            *((float4*)&g_h[(size_t)(row0 + rlo + 1) * D + c0]) = vhi;
    }
}

// ---------------------------------------------------------------------------
// Binning pipeline: counting sort of edges by dst
// ---------------------------------------------------------------------------
__global__ void hist_kernel(const int* __restrict__ ei, int E) {
    int i = blockIdx.x * blockDim.x + threadIdx.x;
    int stride = gridDim.x * blockDim.x;
    for (; i < E; i += stride) {
        atomicAdd(&g_count[ei[E + i]], 1);   // dst row of edge_index
    }
}

__global__ void scan1_kernel(int N) {
    __shared__ int s[CHUNK];
    int i = blockIdx.x * CHUNK + threadIdx.x;
    s[threadIdx.x] = (i < N) ? g_count[i] : 0;
    __syncthreads();
    #pragma unroll
    for (int d = CHUNK / 2; d > 0; d >>= 1) {
        if (threadIdx.x < d) s[threadIdx.x] += s[threadIdx.x + d];
        __syncthreads();
    }
    if (threadIdx.x == 0) g_bsum[blockIdx.x] = s[0];
}

__global__ void scan2_kernel(int NB) {
    __shared__ int s[MAX_BLK + 1];
    if (threadIdx.x < NB) s[threadIdx.x] = g_bsum[threadIdx.x];
    __syncthreads();
    if (threadIdx.x == 0) {
        int run = 0;
        for (int b = 0; b < NB; b++) { int v = s[b]; s[b] = run; run += v; }
    }
    __syncthreads();
    if (threadIdx.x < NB) g_boff[threadIdx.x] = s[threadIdx.x];
}

__global__ void scan3_kernel(int N) {
    __shared__ int buf0[CHUNK];
    __shared__ int buf1[CHUNK];
    int i = blockIdx.x * CHUNK + threadIdx.x;
    int val = (i < N) ? g_count[i] : 0;

    int* cur = buf0; int* nxt = buf1;
    cur[threadIdx.x] = val;
    __syncthreads();
    #pragma unroll
    for (int d = 1; d < CHUNK; d <<= 1) {             // Hillis-Steele inclusive
        int v = cur[threadIdx.x];
        if (threadIdx.x >= d) v += cur[threadIdx.x - d];
        nxt[threadIdx.x] = v;
        __syncthreads();
        int* t = cur; cur = nxt; nxt = t;
    }
    if (i < N) {
        int excl = cur[threadIdx.x] - val + g_boff[blockIdx.x];
        g_off[i]    = excl;
        g_cursor[i] = excl;
        if (i == N - 1) g_off[N] = excl + val;
    }
}

__global__ void binfill_kernel(const int* __restrict__ ei, int E) {
    int i = blockIdx.x * blockDim.x + threadIdx.x;
    int stride = gridDim.x * blockDim.x;
    for (; i < E; i += stride) {
        int src = ei[i];
        int dst = ei[E + i];
        int pos = atomicAdd(&g_cursor[dst], 1);
        g_binned_src[pos] = src;
    }
}

// ---------------------------------------------------------------------------
// Gather: one warp per destination node, no atomics, single coalesced store.
// ---------------------------------------------------------------------------
__global__ void __launch_bounds__(256)
gather_kernel(float* __restrict__ out, int N) {
    const int node = blockIdx.x * 8 + (threadIdx.x >> 5);
    if (node >= N) return;
    const int lane = threadIdx.x & 31;

    const int s = __ldg(&g_off[node]);
    const int e = __ldg(&g_off[node + 1]);

    float4 a0 = {0.f,0.f,0.f,0.f};
    float4 a1 = {0.f,0.f,0.f,0.f};
    float4 a2 = {0.f,0.f,0.f,0.f};
    float4 a3 = {0.f,0.f,0.f,0.f};

    for (int j = s; j < e; j += 32) {
        const int m = min(32, e - j);
        int srcv = (j + lane < e) ? __ldg(&g_binned_src[j + lane]) : 0;

        int b = 0;
        for (; b + 4 <= m; b += 4) {
            int s0 = __shfl_sync(0xFFFFFFFFu, srcv, b);
            int s1 = __shfl_sync(0xFFFFFFFFu, srcv, b + 1);
            int s2 = __shfl_sync(0xFFFFFFFFu, srcv, b + 2);
            int s3 = __shfl_sync(0xFFFFFFFFu, srcv, b + 3);
            float4 v0 = __ldg((const float4*)&g_h[(size_t)s0 * D] + lane);
            float4 v1 = __ldg((const float4*)&g_h[(size_t)s1 * D] + lane);
            float4 v2 = __ldg((const float4*)&g_h[(size_t)s2 * D] + lane);
            float4 v3 = __ldg((const float4*)&g_h[(size_t)s3 * D] + lane);
            a0.x += v0.x; a0.y += v0.y; a0.z += v0.z; a0.w += v0.w;
            a1.x += v1.x; a1.y += v1.y; a1.z += v1.z; a1.w += v1.w;
            a2.x += v2.x; a2.y += v2.y; a2.z += v2.z; a2.w += v2.w;
            a3.x += v3.x; a3.y += v3.y; a3.z += v3.z; a3.w += v3.w;
        }
        for (; b < m; b++) {
            int sb = __shfl_sync(0xFFFFFFFFu, srcv, b);
            float4 v = __ldg((const float4*)&g_h[(size_t)sb * D] + lane);
            a0.x += v.x; a0.y += v.y; a0.z += v.z; a0.w += v.w;
        }
    }

    a0.x += a1.x + a2.x + a3.x;
    a0.y += a1.y + a2.y + a3.y;
    a0.z += a1.z + a2.z + a3.z;
    a0.w += a1.w + a2.w + a3.w;

    *((float4*)&out[(size_t)node * D] + lane) = a0;
}

// ---------------------------------------------------------------------------
extern "C" void kernel_launch(void* const* d_in, const int* in_sizes, int n_in,
                              void* d_out, int out_size) {
    const float* x  = (const float*)d_in[0];   // [N, 128] fp32
    const float* W  = (const float*)d_in[1];   // [128, 128] fp32
    const int*   ei = (const int*)d_in[2];     // [2, E] int32
    float* out = (float*)d_out;                // [N, 128] fp32

    const int N  = in_sizes[0] / D;
    const int E  = in_sizes[2] / 2;
    const int NB = (N + CHUNK - 1) / CHUNK;

    // One-time handle creation (host objects only; no device memory).
    static cudaStream_t s_gemm = nullptr;
    static cudaEvent_t  ev_fork = nullptr, ev_gemm = nullptr;
    if (!s_gemm) {
        cudaStreamCreateWithFlags(&s_gemm, cudaStreamNonBlocking);
        cudaEventCreateWithFlags(&ev_fork, cudaEventDisableTiming);
        cudaEventCreateWithFlags(&ev_gemm, cudaEventDisableTiming);
        cudaFuncSetAttribute(gemm_kernel,
                             cudaFuncAttributeMaxDynamicSharedMemorySize,
                             GEMM_SMEM_BYTES);
    }

    void* count_ptr = nullptr;
    cudaGetSymbolAddress(&count_ptr, g_count);

    // ---- Fork: GEMM on side stream, binning chain on the main stream ----
    cudaEventRecord(ev_fork, 0);
    cudaStreamWaitEvent(s_gemm, ev_fork, 0);

    gemm_kernel<<<(N + ROWS_PB - 1) / ROWS_PB, 256, GEMM_SMEM_BYTES, s_gemm>>>(x, W, N);
    cudaEventRecord(ev_gemm, s_gemm);

    // Binning chain (independent of GEMM)
    cudaMemsetAsync(count_ptr, 0, (size_t)N * sizeof(int), 0);
    hist_kernel<<<592, 256>>>(ei, E);
    scan1_kernel<<<NB, CHUNK>>>(N);
    scan2_kernel<<<1, 128>>>(NB);
    scan3_kernel<<<NB, CHUNK>>>(N);
    binfill_kernel<<<592, 256>>>(ei, E);

    // ---- Join: gather needs both g_h and the bins ----
    cudaStreamWaitEvent(0, ev_gemm, 0);
    gather_kernel<<<(N + 7) / 8, 256>>>(out, N);
}

// round 14
// speedup vs baseline: 1.2531x; 1.0885x over previous
#include <cuda_runtime.h>
#include <cuda_fp16.h>
#include <cuda_bf16.h>

// Problem constants (verified against in_sizes at launch)
#define D        128
#define MAX_N    100000
#define MAX_E    3200000
#define CHUNK    1024
#define MAX_BLK  ((MAX_N + CHUNK - 1) / CHUNK)   // 98

// Scratch (__device__ globals per allocation rules)
__device__ __half g_hh[(size_t)MAX_N * D];    // 25.6 MB: h = x @ W^T in fp16
__device__ int    g_count[MAX_N];             // per-dst degree
__device__ int    g_off[MAX_N + 1];           // exclusive offsets
__device__ int    g_cursor[MAX_N];            // fill cursors
__device__ int    g_bsum[MAX_BLK];            // per-block sums
__device__ int    g_boff[MAX_BLK];            // per-block offsets
__device__ int    g_binned_src[MAX_E];        // edges sorted by dst

// ---------------------------------------------------------------------------
// Kernel 1: h = x @ W^T   (fp32 SIMT with packed fma.rn.f32x2, fp16 output)
// 64 rows/block, 256 threads (8 warps), 8 rows/warp (4 row-PAIRS), 4 cols/lane.
// ---------------------------------------------------------------------------
#define WT_LD   132
#define XS_LD   66
#define ROWS_PB 64
#define GEMM_SMEM_BYTES ((128 * WT_LD + 128 * XS_LD) * 4)   // 101376 B

__device__ __forceinline__ unsigned long long pack2(float f) {
    unsigned long long r;
    unsigned int u = __float_as_uint(f);
    asm("mov.b64 %0, {%1, %1};" : "=l"(r) : "r"(u));
    return r;
}
__device__ __forceinline__ void fma2(unsigned long long& d,
                                     unsigned long long a,
                                     unsigned long long b) {
    asm("fma.rn.f32x2 %0, %1, %2, %0;" : "+l"(d) : "l"(a), "l"(b));
}
__device__ __forceinline__ void unpack2(unsigned long long v, float& lo, float& hi) {
    unsigned int ulo, uhi;
    asm("mov.b64 {%0, %1}, %2;" : "=r"(ulo), "=r"(uhi) : "l"(v));
    lo = __uint_as_float(ulo);
    hi = __uint_as_float(uhi);
}

__global__ void __launch_bounds__(256, 2)
gemm_kernel(const float* __restrict__ x, const float* __restrict__ W, int N) {
    extern __shared__ float smem[];
    float* Wt  = smem;                     // [128][WT_LD]  Wt[k][c] = W[c][k]
    float* xst = smem + 128 * WT_LD;       // [128][XS_LD]  xst[k][r] = x[row0+r][k]

    const int tid = threadIdx.x;
    const int row0 = blockIdx.x * ROWS_PB;
    const int nrows = min(ROWS_PB, N - row0);

    #pragma unroll 4
    for (int i = tid; i < 128 * 128; i += 256) {
        int c = i >> 7, k = i & 127;
        Wt[k * WT_LD + c] = W[i];
    }
    #pragma unroll 4
    for (int i = tid; i < ROWS_PB * 128; i += 256) {
        int r = i >> 7, k = i & 127;
        xst[k * XS_LD + r] = (r < nrows) ? x[(size_t)row0 * D + i] : 0.f;
    }
    __syncthreads();

    const int warp = tid >> 5, lane = tid & 31;
    const int r0 = warp * 8;               // 8 rows = 4 row-pairs per warp
    const int c0 = lane * 4;               // 4 cols per lane

    unsigned long long acc[4][4];          // [row-pair][col] packed f32x2 (lo=even row)
    #pragma unroll
    for (int p = 0; p < 4; p++)
        #pragma unroll
        for (int c = 0; c < 4; c++) acc[p][c] = 0ull;

    #pragma unroll 4
    for (int k = 0; k < 128; k++) {
        float4 wv = *(const float4*)&Wt[k * WT_LD + c0];
        unsigned long long w0 = pack2(wv.x);
        unsigned long long w1 = pack2(wv.y);
        unsigned long long w2 = pack2(wv.z);
        unsigned long long w3 = pack2(wv.w);

        const unsigned long long* xp =
            (const unsigned long long*)&xst[k * XS_LD + r0];
        unsigned long long x0 = xp[0];
        unsigned long long x1 = xp[1];
        unsigned long long x2 = xp[2];
        unsigned long long x3 = xp[3];

        fma2(acc[0][0], x0, w0); fma2(acc[0][1], x0, w1);
        fma2(acc[0][2], x0, w2); fma2(acc[0][3], x0, w3);
        fma2(acc[1][0], x1, w0); fma2(acc[1][1], x1, w1);
        fma2(acc[1][2], x1, w2); fma2(acc[1][3], x1, w3);
        fma2(acc[2][0], x2, w0); fma2(acc[2][1], x2, w1);
        fma2(acc[2][2], x2, w2); fma2(acc[2][3], x2, w3);
        fma2(acc[3][0], x3, w0); fma2(acc[3][1], x3, w1);
        fma2(acc[3][2], x3, w2); fma2(acc[3][3], x3, w3);
    }

    #pragma unroll
    for (int p = 0; p < 4; p++) {
        const int rlo = r0 + 2 * p;
        float4 vlo, vhi;
        unpack2(acc[p][0], vlo.x, vhi.x);
        unpack2(acc[p][1], vlo.y, vhi.y);
        unpack2(acc[p][2], vlo.z, vhi.z);
        unpack2(acc[p][3], vlo.w, vhi.w);

        __half2 lo01 = __floats2half2_rn(vlo.x, vlo.y);
        __half2 lo23 = __floats2half2_rn(vlo.z, vlo.w);
        __half2 hi01 = __floats2half2_rn(vhi.x, vhi.y);
        __half2 hi23 = __floats2half2_rn(vhi.z, vhi.w);

        if (rlo < nrows) {
            uint2 u;
            u.x = *reinterpret_cast<unsigned int*>(&lo01);
            u.y = *reinterpret_cast<unsigned int*>(&lo23);
            *reinterpret_cast<uint2*>(&g_hh[(size_t)(row0 + rlo) * D + c0]) = u;
        }
        if (rlo + 1 < nrows) {
            uint2 u;
            u.x = *reinterpret_cast<unsigned int*>(&hi01);
            u.y = *reinterpret_cast<unsigned int*>(&hi23);
            *reinterpret_cast<uint2*>(&g_hh[(size_t)(row0 + rlo + 1) * D + c0]) = u;
        }
    }
}

// ---------------------------------------------------------------------------
// Binning pipeline: counting sort of edges by dst
// ---------------------------------------------------------------------------
__global__ void hist_kernel(const int* __restrict__ ei, int E) {
    int i = blockIdx.x * blockDim.x + threadIdx.x;
    int stride = gridDim.x * blockDim.x;
    for (; i < E; i += stride) {
        atomicAdd(&g_count[ei[E + i]], 1);
    }
}

__global__ void scan1_kernel(int N) {
    __shared__ int s[CHUNK];
    int i = blockIdx.x * CHUNK + threadIdx.x;
    s[threadIdx.x] = (i < N) ? g_count[i] : 0;
    __syncthreads();
    #pragma unroll
    for (int d = CHUNK / 2; d > 0; d >>= 1) {
        if (threadIdx.x < d) s[threadIdx.x] += s[threadIdx.x + d];
        __syncthreads();
    }
    if (threadIdx.x == 0) g_bsum[blockIdx.x] = s[0];
}

__global__ void scan2_kernel(int NB) {
    __shared__ int s[MAX_BLK + 1];
    if (threadIdx.x < NB) s[threadIdx.x] = g_bsum[threadIdx.x];
    __syncthreads();
    if (threadIdx.x == 0) {
        int run = 0;
        for (int b = 0; b < NB; b++) { int v = s[b]; s[b] = run; run += v; }
    }
    __syncthreads();
    if (threadIdx.x < NB) g_boff[threadIdx.x] = s[threadIdx.x];
}

__global__ void scan3_kernel(int N) {
    __shared__ int buf0[CHUNK];
    __shared__ int buf1[CHUNK];
    int i = blockIdx.x * CHUNK + threadIdx.x;
    int val = (i < N) ? g_count[i] : 0;

    int* cur = buf0; int* nxt = buf1;
    cur[threadIdx.x] = val;
    __syncthreads();
    #pragma unroll
    for (int d = 1; d < CHUNK; d <<= 1) {
        int v = cur[threadIdx.x];
        if (threadIdx.x >= d) v += cur[threadIdx.x - d];
        nxt[threadIdx.x] = v;
        __syncthreads();
        int* t = cur; cur = nxt; nxt = t;
    }
    if (i < N) {
        int excl = cur[threadIdx.x] - val + g_boff[blockIdx.x];
        g_off[i]    = excl;
        g_cursor[i] = excl;
        if (i == N - 1) g_off[N] = excl + val;
    }
}

__global__ void binfill_kernel(const int* __restrict__ ei, int E) {
    int i = blockIdx.x * blockDim.x + threadIdx.x;
    int stride = gridDim.x * blockDim.x;
    for (; i < E; i += stride) {
        int src = ei[i];
        int dst = ei[E + i];
        int pos = atomicAdd(&g_cursor[dst], 1);
        g_binned_src[pos] = src;
    }
}

// ---------------------------------------------------------------------------
// Gather: one warp per destination node, fp16 payload, fp32 accumulation.
// Lane handles 4 columns: loads uint2 (4 halfs = 8B) per edge; warp reads
// 256B = 2 full L2 lines per edge. Accumulates fp32, stores one float4.
// ---------------------------------------------------------------------------
__global__ void __launch_bounds__(256)
gather_kernel(float* __restrict__ out, int N) {
    const int node = blockIdx.x * 8 + (threadIdx.x >> 5);
    if (node >= N) return;
    const int lane = threadIdx.x & 31;

    const int s = __ldg(&g_off[node]);
    const int e = __ldg(&g_off[node + 1]);

    float4 a0 = {0.f,0.f,0.f,0.f};
    float4 a1 = {0.f,0.f,0.f,0.f};
    float4 a2 = {0.f,0.f,0.f,0.f};
    float4 a3 = {0.f,0.f,0.f,0.f};

    for (int j = s; j < e; j += 32) {
        const int m = min(32, e - j);
        int srcv = (j + lane < e) ? __ldg(&g_binned_src[j + lane]) : 0;

        int b = 0;
        for (; b + 4 <= m; b += 4) {
            int s0 = __shfl_sync(0xFFFFFFFFu, srcv, b);
            int s1 = __shfl_sync(0xFFFFFFFFu, srcv, b + 1);
            int s2 = __shfl_sync(0xFFFFFFFFu, srcv, b + 2);
            int s3 = __shfl_sync(0xFFFFFFFFu, srcv, b + 3);
            uint2 u0 = __ldg((const uint2*)&g_hh[(size_t)s0 * D] + lane);
            uint2 u1 = __ldg((const uint2*)&g_hh[(size_t)s1 * D] + lane);
            uint2 u2 = __ldg((const uint2*)&g_hh[(size_t)s2 * D] + lane);
            uint2 u3 = __ldg((const uint2*)&g_hh[(size_t)s3 * D] + lane);

            float2 f;
            f = __half22float2(*(__half2*)&u0.x); a0.x += f.x; a0.y += f.y;
            f = __half22float2(*(__half2*)&u0.y); a0.z += f.x; a0.w += f.y;
            f = __half22float2(*(__half2*)&u1.x); a1.x += f.x; a1.y += f.y;
            f = __half22float2(*(__half2*)&u1.y); a1.z += f.x; a1.w += f.y;
            f = __half22float2(*(__half2*)&u2.x); a2.x += f.x; a2.y += f.y;
            f = __half22float2(*(__half2*)&u2.y); a2.z += f.x; a2.w += f.y;
            f = __half22float2(*(__half2*)&u3.x); a3.x += f.x; a3.y += f.y;
            f = __half22float2(*(__half2*)&u3.y); a3.z += f.x; a3.w += f.y;
        }
        for (; b < m; b++) {
            int sb = __shfl_sync(0xFFFFFFFFu, srcv, b);
            uint2 u = __ldg((const uint2*)&g_hh[(size_t)sb * D] + lane);
            float2 f;
            f = __half22float2(*(__half2*)&u.x); a0.x += f.x; a0.y += f.y;
            f = __half22float2(*(__half2*)&u.y); a0.z += f.x; a0.w += f.y;
        }
    }

    a0.x += a1.x + a2.x + a3.x;
    a0.y += a1.y + a2.y + a3.y;
    a0.z += a1.z + a2.z + a3.z;
    a0.w += a1.w + a2.w + a3.w;

    *((float4*)&out[(size_t)node * D] + lane) = a0;
}

// ---------------------------------------------------------------------------
extern "C" void kernel_launch(void* const* d_in, const int* in_sizes, int n_in,
                              void* d_out, int out_size) {
    const float* x  = (const float*)d_in[0];   // [N, 128] fp32
    const float* W  = (const float*)d_in[1];   // [128, 128] fp32
    const int*   ei = (const int*)d_in[2];     // [2, E] int32
    float* out = (float*)d_out;                // [N, 128] fp32

    const int N  = in_sizes[0] / D;
    const int E  = in_sizes[2] / 2;
    const int NB = (N + CHUNK - 1) / CHUNK;

    static cudaStream_t s_gemm = nullptr;
    static cudaEvent_t  ev_fork = nullptr, ev_gemm = nullptr;
    if (!s_gemm) {
        cudaStreamCreateWithFlags(&s_gemm, cudaStreamNonBlocking);
        cudaEventCreateWithFlags(&ev_fork, cudaEventDisableTiming);
        cudaEventCreateWithFlags(&ev_gemm, cudaEventDisableTiming);
        cudaFuncSetAttribute(gemm_kernel,
                             cudaFuncAttributeMaxDynamicSharedMemorySize,
                             GEMM_SMEM_BYTES);
    }

    void* count_ptr = nullptr;
    cudaGetSymbolAddress(&count_ptr, g_count);

    // ---- Fork: GEMM on side stream, binning chain on the main stream ----
    cudaEventRecord(ev_fork, 0);
    cudaStreamWaitEvent(s_gemm, ev_fork, 0);

    gemm_kernel<<<(N + ROWS_PB - 1) / ROWS_PB, 256, GEMM_SMEM_BYTES, s_gemm>>>(x, W, N);
    cudaEventRecord(ev_gemm, s_gemm);

    // Binning chain (independent of GEMM)
    cudaMemsetAsync(count_ptr, 0, (size_t)N * sizeof(int), 0);
    hist_kernel<<<592, 256>>>(ei, E);
    scan1_kernel<<<NB, CHUNK>>>(N);
    scan2_kernel<<<1, 128>>>(NB);
    scan3_kernel<<<NB, CHUNK>>>(N);
    binfill_kernel<<<592, 256>>>(ei, E);

    // ---- Join: gather needs both g_hh and the bins ----
    cudaStreamWaitEvent(0, ev_gemm, 0);
    gather_kernel<<<(N + 7) / 8, 256>>>(out, N);
}

// round 17
// speedup vs baseline: 1.4254x; 1.1375x over previous
#include <cuda_runtime.h>
#include <cuda_fp16.h>
#include <cuda_bf16.h>
#include <cstdint>

// Problem constants (verified against in_sizes at launch)
#define D        128
#define MAX_N    100000
#define MAX_E    3200000
#define CHUNK    1024
#define MAX_BLK  ((MAX_N + CHUNK - 1) / CHUNK)   // 98

// Scratch (__device__ globals per allocation rules)
__device__ __half g_hh[(size_t)MAX_N * D];    // 25.6 MB: h = x @ W^T in fp16
__device__ int    g_count[MAX_N];             // per-dst degree
__device__ int    g_off[MAX_N + 1];           // exclusive offsets
__device__ int    g_cursor[MAX_N];            // fill cursors
__device__ int    g_bsum[MAX_BLK];            // per-block sums
__device__ int    g_boff[MAX_BLK];            // per-block offsets
__device__ int    g_binned_src[MAX_E];        // edges sorted by dst

// ---------------------------------------------------------------------------
// Kernel 1: h = x @ W^T via mma.sync m16n8k16 fp16 tensor cores (portable ISA,
// no tcgen05 — harness emits compute_103 PTX). Error-compensated:
//   D = Ah*Bh + Al*Bh + Ah*Bl,  A = x hi/lo fp16 split, B = W hi/lo split.
// CTA tile: 128 rows x 128 cols x K=128. 8 warps (4x2), warp tile 32x64.
// W stored [n][k] with k contiguous == col-major KxN -> plain ldmatrix for B.
// ---------------------------------------------------------------------------
#define LDA      136                           // 128 + 8 halfs pad (272 B rows)
#define OFF_AH   0
#define OFF_AL   (128 * LDA * 2)               // 34816
#define OFF_BH   (2 * 128 * LDA * 2)
#define OFF_BL   (3 * 128 * LDA * 2)
#define MMA_SMEM (4 * 128 * LDA * 2)           // 139264 B

__device__ __forceinline__ uint32_t smem_u32(const void* p) {
    uint32_t a;
    asm("{ .reg .u64 t; cvta.to.shared.u64 t, %1; cvt.u32.u64 %0, t; }"
        : "=r"(a) : "l"(p));
    return a;
}

__device__ __forceinline__ void ldsm_x4(uint32_t addr, uint32_t& r0, uint32_t& r1,
                                        uint32_t& r2, uint32_t& r3) {
    asm volatile("ldmatrix.sync.aligned.m8n8.x4.shared.b16 {%0,%1,%2,%3}, [%4];"
                 : "=r"(r0), "=r"(r1), "=r"(r2), "=r"(r3) : "r"(addr));
}

__device__ __forceinline__ void mma16816(float* c, const uint32_t* a,
                                         uint32_t b0, uint32_t b1) {
    asm volatile(
        "mma.sync.aligned.m16n8k16.row.col.f32.f16.f16.f32 "
        "{%0,%1,%2,%3}, {%4,%5,%6,%7}, {%8,%9}, {%0,%1,%2,%3};"
        : "+f"(c[0]), "+f"(c[1]), "+f"(c[2]), "+f"(c[3])
        : "r"(a[0]), "r"(a[1]), "r"(a[2]), "r"(a[3]), "r"(b0), "r"(b1));
}

__global__ void __launch_bounds__(256, 1)
mma_gemm_kernel(const float* __restrict__ x, const float* __restrict__ W, int N) {
    extern __shared__ char smem[];
    const uint32_t sb = smem_u32(smem);
    const int tid  = threadIdx.x;
    const int wid  = tid >> 5;
    const int lane = tid & 31;
    const int row0 = blockIdx.x * 128;
    const int nrows = min(128, N - row0);

    __half* Ah = (__half*)(smem + OFF_AH);
    __half* Al = (__half*)(smem + OFF_AL);
    __half* Bh = (__half*)(smem + OFF_BH);
    __half* Bl = (__half*)(smem + OFF_BL);

    // ---- Stage x and W as hi/lo fp16 splits (coalesced global float2 reads) ----
    #pragma unroll 4
    for (int i = tid; i < 128 * 64; i += 256) {
        const int r = i >> 6, p = i & 63;
        const int so = r * LDA + 2 * p;

        float2 xv = (r < nrows)
            ? *(const float2*)&x[(size_t)(row0 + r) * D + 2 * p]
            : make_float2(0.f, 0.f);
        __half2 xh = __floats2half2_rn(xv.x, xv.y);
        float2 xb = __half22float2(xh);
        __half2 xl = __floats2half2_rn(xv.x - xb.x, xv.y - xb.y);
        *(__half2*)&Ah[so] = xh;
        *(__half2*)&Al[so] = xl;

        float2 wv = *(const float2*)&W[(size_t)r * D + 2 * p];
        __half2 wh = __floats2half2_rn(wv.x, wv.y);
        float2 wb = __half22float2(wh);
        __half2 wl = __floats2half2_rn(wv.x - wb.x, wv.y - wb.y);
        *(__half2*)&Bh[so] = wh;
        *(__half2*)&Bl[so] = wl;
    }
    __syncthreads();

    // ---- Warp tiling: warp (wid&3) -> m0, (wid>>2) -> n0 ----
    const int m0 = (wid & 3) * 32;
    const int n0 = (wid >> 2) * 64;

    float acc[2][8][4];
    #pragma unroll
    for (int mt = 0; mt < 2; mt++)
        #pragma unroll
        for (int nt = 0; nt < 8; nt++)
            #pragma unroll
            for (int q = 0; q < 4; q++) acc[mt][nt][q] = 0.f;

    // ldmatrix row addresses: threads 0-15 -> rows at k-offset 0, 16-31 -> +8
    const int lrow  = lane & 15;
    const int lkoff = (lane >> 4) * 8;

    const uint32_t aAh = sb + OFF_AH + (uint32_t)(((m0 + lrow) * LDA + lkoff) * 2);
    const uint32_t aAl = sb + OFF_AL + (uint32_t)(((m0 + lrow) * LDA + lkoff) * 2);
    const uint32_t aBh = sb + OFF_BH + (uint32_t)(((n0 + lrow) * LDA + lkoff) * 2);
    const uint32_t aBl = sb + OFF_BL + (uint32_t)(((n0 + lrow) * LDA + lkoff) * 2);

    #pragma unroll
    for (int k0 = 0; k0 < 128; k0 += 16) {
        const uint32_t kb = (uint32_t)(k0 * 2);

        uint32_t ah[2][4], al[2][4];
        ldsm_x4(aAh + kb,                ah[0][0], ah[0][1], ah[0][2], ah[0][3]);
        ldsm_x4(aAh + 16 * LDA * 2 + kb, ah[1][0], ah[1][1], ah[1][2], ah[1][3]);
        ldsm_x4(aAl + kb,                al[0][0], al[0][1], al[0][2], al[0][3]);
        ldsm_x4(aAl + 16 * LDA * 2 + kb, al[1][0], al[1][1], al[1][2], al[1][3]);

        uint32_t bh[8][2], bl[8][2];
        #pragma unroll
        for (int np = 0; np < 4; np++) {
            uint32_t q0, q1, q2, q3;
            ldsm_x4(aBh + np * 16 * LDA * 2 + kb, q0, q1, q2, q3);
            bh[2*np][0] = q0; bh[2*np][1] = q2;
            bh[2*np+1][0] = q1; bh[2*np+1][1] = q3;
            ldsm_x4(aBl + np * 16 * LDA * 2 + kb, q0, q1, q2, q3);
            bl[2*np][0] = q0; bl[2*np][1] = q2;
            bl[2*np+1][0] = q1; bl[2*np+1][1] = q3;
        }

        #pragma unroll
        for (int mt = 0; mt < 2; mt++) {
            #pragma unroll
            for (int nt = 0; nt < 8; nt++) {
                mma16816(acc[mt][nt], ah[mt], bh[nt][0], bh[nt][1]);
                mma16816(acc[mt][nt], al[mt], bh[nt][0], bh[nt][1]);
                mma16816(acc[mt][nt], ah[mt], bl[nt][0], bl[nt][1]);
            }
        }
    }

    // ---- Epilogue: fp32 acc -> fp16 store to g_hh ----
    const int g   = lane >> 2;
    const int tig = lane & 3;
    #pragma unroll
    for (int mt = 0; mt < 2; mt++) {
        #pragma unroll
        for (int nt = 0; nt < 8; nt++) {
            const int r = m0 + mt * 16 + g;
            const int c = n0 + nt * 8 + tig * 2;
            __half2 h0 = __floats2half2_rn(acc[mt][nt][0], acc[mt][nt][1]);
            __half2 h1 = __floats2half2_rn(acc[mt][nt][2], acc[mt][nt][3]);
            if (r < nrows)
                *(__half2*)&g_hh[(size_t)(row0 + r) * D + c] = h0;
            if (r + 8 < nrows)
                *(__half2*)&g_hh[(size_t)(row0 + r + 8) * D + c] = h1;
        }
    }
}

// ---------------------------------------------------------------------------
// Binning pipeline: counting sort of edges by dst
// ---------------------------------------------------------------------------
__global__ void hist_kernel(const int* __restrict__ ei, int E) {
    int i = blockIdx.x * blockDim.x + threadIdx.x;
    int stride = gridDim.x * blockDim.x;
    for (; i < E; i += stride) {
        atomicAdd(&g_count[ei[E + i]], 1);
    }
}

__global__ void scan1_kernel(int N) {
    __shared__ int s[CHUNK];
    int i = blockIdx.x * CHUNK + threadIdx.x;
    s[threadIdx.x] = (i < N) ? g_count[i] : 0;
    __syncthreads();
    #pragma unroll
    for (int d = CHUNK / 2; d > 0; d >>= 1) {
        if (threadIdx.x < d) s[threadIdx.x] += s[threadIdx.x + d];
        __syncthreads();
    }
    if (threadIdx.x == 0) g_bsum[blockIdx.x] = s[0];
}

__global__ void scan2_kernel(int NB) {
    __shared__ int s[MAX_BLK + 1];
    if (threadIdx.x < NB) s[threadIdx.x] = g_bsum[threadIdx.x];
    __syncthreads();
    if (threadIdx.x == 0) {
        int run = 0;
        for (int b = 0; b < NB; b++) { int v = s[b]; s[b] = run; run += v; }
    }
    __syncthreads();
    if (threadIdx.x < NB) g_boff[threadIdx.x] = s[threadIdx.x];
}

__global__ void scan3_kernel(int N) {
    __shared__ int buf0[CHUNK];
    __shared__ int buf1[CHUNK];
    int i = blockIdx.x * CHUNK + threadIdx.x;
    int val = (i < N) ? g_count[i] : 0;

    int* cur = buf0; int* nxt = buf1;
    cur[threadIdx.x] = val;
    __syncthreads();
    #pragma unroll
    for (int d = 1; d < CHUNK; d <<= 1) {
        int v = cur[threadIdx.x];
        if (threadIdx.x >= d) v += cur[threadIdx.x - d];
        nxt[threadIdx.x] = v;
        __syncthreads();
        int* t = cur; cur = nxt; nxt = t;
    }
    if (i < N) {
        int excl = cur[threadIdx.x] - val + g_boff[blockIdx.x];
        g_off[i]    = excl;
        g_cursor[i] = excl;
        if (i == N - 1) g_off[N] = excl + val;
    }
}

__global__ void binfill_kernel(const int* __restrict__ ei, int E) {
    int i = blockIdx.x * blockDim.x + threadIdx.x;
    int stride = gridDim.x * blockDim.x;
    for (; i < E; i += stride) {
        int src = ei[i];
        int dst = ei[E + i];
        int pos = atomicAdd(&g_cursor[dst], 1);
        g_binned_src[pos] = src;
    }
}

// ---------------------------------------------------------------------------
// Gather: one warp per destination node, fp16 payload, fp32 accumulation.
// ---------------------------------------------------------------------------
__global__ void __launch_bounds__(256)
gather_kernel(float* __restrict__ out, int N) {
    const int node = blockIdx.x * 8 + (threadIdx.x >> 5);
    if (node >= N) return;
    const int lane = threadIdx.x & 31;

    const int s = __ldg(&g_off[node]);
    const int e = __ldg(&g_off[node + 1]);

    float4 a0 = {0.f,0.f,0.f,0.f};
    float4 a1 = {0.f,0.f,0.f,0.f};
    float4 a2 = {0.f,0.f,0.f,0.f};
    float4 a3 = {0.f,0.f,0.f,0.f};

    for (int j = s; j < e; j += 32) {
        const int m = min(32, e - j);
        int srcv = (j + lane < e) ? __ldg(&g_binned_src[j + lane]) : 0;

        int b = 0;
        for (; b + 4 <= m; b += 4) {
            int s0 = __shfl_sync(0xFFFFFFFFu, srcv, b);
            int s1 = __shfl_sync(0xFFFFFFFFu, srcv, b + 1);
            int s2 = __shfl_sync(0xFFFFFFFFu, srcv, b + 2);
            int s3 = __shfl_sync(0xFFFFFFFFu, srcv, b + 3);
            uint2 u0 = __ldg((const uint2*)&g_hh[(size_t)s0 * D] + lane);
            uint2 u1 = __ldg((const uint2*)&g_hh[(size_t)s1 * D] + lane);
            uint2 u2 = __ldg((const uint2*)&g_hh[(size_t)s2 * D] + lane);
            uint2 u3 = __ldg((const uint2*)&g_hh[(size_t)s3 * D] + lane);

            float2 f;
            f = __half22float2(*(__half2*)&u0.x); a0.x += f.x; a0.y += f.y;
            f = __half22float2(*(__half2*)&u0.y); a0.z += f.x; a0.w += f.y;
            f = __half22float2(*(__half2*)&u1.x); a1.x += f.x; a1.y += f.y;
            f = __half22float2(*(__half2*)&u1.y); a1.z += f.x; a1.w += f.y;
            f = __half22float2(*(__half2*)&u2.x); a2.x += f.x; a2.y += f.y;
            f = __half22float2(*(__half2*)&u2.y); a2.z += f.x; a2.w += f.y;
            f = __half22float2(*(__half2*)&u3.x); a3.x += f.x; a3.y += f.y;
            f = __half22float2(*(__half2*)&u3.y); a3.z += f.x; a3.w += f.y;
        }
        for (; b < m; b++) {
            int sb = __shfl_sync(0xFFFFFFFFu, srcv, b);
            uint2 u = __ldg((const uint2*)&g_hh[(size_t)sb * D] + lane);
            float2 f;
            f = __half22float2(*(__half2*)&u.x); a0.x += f.x; a0.y += f.y;
            f = __half22float2(*(__half2*)&u.y); a0.z += f.x; a0.w += f.y;
        }
    }

    a0.x += a1.x + a2.x + a3.x;
    a0.y += a1.y + a2.y + a3.y;
    a0.z += a1.z + a2.z + a3.z;
    a0.w += a1.w + a2.w + a3.w;

    *((float4*)&out[(size_t)node * D] + lane) = a0;
}

// ---------------------------------------------------------------------------
extern "C" void kernel_launch(void* const* d_in, const int* in_sizes, int n_in,
                              void* d_out, int out_size) {
    const float* x  = (const float*)d_in[0];   // [N, 128] fp32
    const float* W  = (const float*)d_in[1];   // [128, 128] fp32
    const int*   ei = (const int*)d_in[2];     // [2, E] int32
    float* out = (float*)d_out;                // [N, 128] fp32

    const int N  = in_sizes[0] / D;
    const int E  = in_sizes[2] / 2;
    const int NB = (N + CHUNK - 1) / CHUNK;

    static cudaStream_t s_gemm = nullptr;
    static cudaEvent_t  ev_fork = nullptr, ev_gemm = nullptr;
    if (!s_gemm) {
        cudaStreamCreateWithFlags(&s_gemm, cudaStreamNonBlocking);
        cudaEventCreateWithFlags(&ev_fork, cudaEventDisableTiming);
        cudaEventCreateWithFlags(&ev_gemm, cudaEventDisableTiming);
        cudaFuncSetAttribute(mma_gemm_kernel,
                             cudaFuncAttributeMaxDynamicSharedMemorySize,
                             MMA_SMEM);
    }

    void* count_ptr = nullptr;
    cudaGetSymbolAddress(&count_ptr, g_count);

    // ---- Fork: MMA GEMM on side stream, binning chain on main stream ----
    cudaEventRecord(ev_fork, 0);
    cudaStreamWaitEvent(s_gemm, ev_fork, 0);

    mma_gemm_kernel<<<(N + 127) / 128, 256, MMA_SMEM, s_gemm>>>(x, W, N);
    cudaEventRecord(ev_gemm, s_gemm);

    // Binning chain (independent of GEMM)
    cudaMemsetAsync(count_ptr, 0, (size_t)N * sizeof(int), 0);
    hist_kernel<<<592, 256>>>(ei, E);
    scan1_kernel<<<NB, CHUNK>>>(N);
    scan2_kernel<<<1, 128>>>(NB);
    scan3_kernel<<<NB, CHUNK>>>(N);
    binfill_kernel<<<592, 256>>>(ei, E);

    // ---- Join: gather needs both g_hh and the bins ----
    cudaStreamWaitEvent(0, ev_gemm, 0);
    gather_kernel<<<(N + 7) / 8, 256>>>(out, N);
}